// round 5
// baseline (speedup 1.0000x reference)
#include <cuda_runtime.h>
#include <math.h>

// Problem constants
#define Bsz 4
#define Sq  2048
#define Dm  768
#define Im  1536
#define Dh  128
#define Mtot (Bsz*Sq)   // 8192

// Scratch (device globals; no allocations allowed)
__device__ float g_V[Mtot*Im];        // silu(x@vW+vb)                  50 MB
__device__ float g_G[Mtot*Im];        // silu(x@gW+gb)                  50 MB
__device__ float g_Q[Mtot*Dh];        // q                               4 MB
__device__ float g_K[Mtot*Dh];        // k                               4 MB
__device__ float g_A[Bsz*Sq*Sq];      // relu^2 causal attention        67 MB
__device__ float g_O[Mtot*Im];        // (A@V)*gate                     50 MB
__device__ float g_bias[Sq];          // bias by causal distance

// ---------------------------------------------------------------------------
// Relative-position bias LUT: bias_d[dist] = rel_emb[bucket(dist)] * sqrt(128)
// ---------------------------------------------------------------------------
__global__ void bias_init_kernel(const float* __restrict__ rel_emb)
{
    int d = blockIdx.x * blockDim.x + threadIdx.x;
    if (d >= Sq) return;
    int bucket;
    if (d < 16) {
        bucket = d;
    } else {
        int v = 16 + (int)(log((double)d / 16.0) / log(8.0) * 16.0);
        bucket = v < 31 ? v : 31;
    }
    g_bias[d] = rel_emb[bucket] * sqrtf((float)Dh);
}

// ---------------------------------------------------------------------------
// Shared SGEMM core: C_tile(128x128) = A(M x K, row-major, lda) @ B(K x N, ldb)
// 256 threads, 8x8 accumulators per thread, BK=8, float4 loads.
// ---------------------------------------------------------------------------
#define BM 128
#define BN 128
#define BKD 8
#define TM 8
#define TN 8
#define NT 256

__device__ __forceinline__ void run_sgemm(
    const float* __restrict__ A, int lda,
    const float* __restrict__ B, int ldb,
    int kStart, int kEnd, float (&acc)[TM][TN])
{
    __shared__ float As[BKD][BM];
    __shared__ float Bs[BKD][BN];
    const int tid  = threadIdx.x;
    const int tr   = tid >> 4;          // 0..15
    const int tc   = tid & 15;          // 0..15
    const int aRow = tid >> 1;          // 0..127
    const int aCol = (tid & 1) << 2;    // 0 or 4
    const int bRow = tid >> 5;          // 0..7
    const int bCol = (tid & 31) << 2;   // 0..124

    const float* Ab = A + (size_t)blockIdx.y * BM * lda;
    const float* Bb = B + (size_t)blockIdx.x * BN;

    for (int k0 = kStart; k0 < kEnd; k0 += BKD) {
        float4 av = *(const float4*)(Ab + (size_t)aRow * lda + k0 + aCol);
        As[aCol + 0][aRow] = av.x;
        As[aCol + 1][aRow] = av.y;
        As[aCol + 2][aRow] = av.z;
        As[aCol + 3][aRow] = av.w;
        *(float4*)&Bs[bRow][bCol] =
            *(const float4*)(Bb + (size_t)(k0 + bRow) * ldb + bCol);
        __syncthreads();
        #pragma unroll
        for (int kk = 0; kk < BKD; kk++) {
            float ra[TM], rb[TN];
            #pragma unroll
            for (int i = 0; i < TM; i++) ra[i] = As[kk][tr * TM + i];
            #pragma unroll
            for (int j = 0; j < TN; j++) rb[j] = Bs[kk][tc * TN + j];
            #pragma unroll
            for (int i = 0; i < TM; i++)
                #pragma unroll
                for (int j = 0; j < TN; j++)
                    acc[i][j] = fmaf(ra[i], rb[j], acc[i][j]);
        }
        __syncthreads();
    }
}

__device__ __forceinline__ float silu_f(float x)
{
    return x / (1.0f + __expf(-x));
}

// ---------------------------------------------------------------------------
// C = silu(X @ W + b)   for V (which=0) and G (which=1).
// Destination resolved in DEVICE code (host must not take __device__ addrs).
// ---------------------------------------------------------------------------
__global__ void __launch_bounds__(NT)
gemm_silu_kernel(const float* __restrict__ X, const float* __restrict__ W,
                 const float* __restrict__ bias, int which)
{
    float* __restrict__ C = which ? g_G : g_V;

    float acc[TM][TN];
    #pragma unroll
    for (int i = 0; i < TM; i++)
        #pragma unroll
        for (int j = 0; j < TN; j++) acc[i][j] = 0.0f;

    run_sgemm(X, Dm, W, Im, 0, Dm, acc);

    const int tid = threadIdx.x;
    const int row0 = blockIdx.y * BM + (tid >> 4) * TM;
    const int col0 = blockIdx.x * BN + (tid & 15) * TN;
    #pragma unroll
    for (int i = 0; i < TM; i++)
        #pragma unroll
        for (int j = 0; j < TN; j++) {
            float s = acc[i][j] + bias[col0 + j];
            C[(size_t)(row0 + i) * Im + col0 + j] = silu_f(s);
        }
}

// ---------------------------------------------------------------------------
// base = silu(X @ inW + inb);  Q = base*qg+qb;  K = base*kg+kb
// ---------------------------------------------------------------------------
__global__ void __launch_bounds__(NT)
gemm_qk_kernel(const float* __restrict__ X, const float* __restrict__ W,
               const float* __restrict__ inb,
               const float* __restrict__ qg, const float* __restrict__ qb,
               const float* __restrict__ kg, const float* __restrict__ kb)
{
    float acc[TM][TN];
    #pragma unroll
    for (int i = 0; i < TM; i++)
        #pragma unroll
        for (int j = 0; j < TN; j++) acc[i][j] = 0.0f;

    run_sgemm(X, Dm, W, Dh, 0, Dm, acc);

    const int tid = threadIdx.x;
    const int row0 = blockIdx.y * BM + (tid >> 4) * TM;
    const int col0 = blockIdx.x * BN + (tid & 15) * TN;   // blockIdx.x == 0
    #pragma unroll
    for (int i = 0; i < TM; i++)
        #pragma unroll
        for (int j = 0; j < TN; j++) {
            int c = col0 + j;
            float base = silu_f(acc[i][j] + inb[c]);
            size_t idx = (size_t)(row0 + i) * Dh + c;
            g_Q[idx] = base * qg[c] + qb[c];
            g_K[idx] = base * kg[c] + kb[c];
        }
}

// ---------------------------------------------------------------------------
// Attention scores: A[b] = relu(Q K^T / sqrt(1536) + bias)^2, causal-masked.
// 64x64 tiles; fully-masked tiles only store zeros.
// ---------------------------------------------------------------------------
__global__ void __launch_bounds__(NT)
scores_kernel()
{
    const int z  = blockIdx.z;
    const int i0 = blockIdx.y * 64;
    const int j0 = blockIdx.x * 64;
    const int tid = threadIdx.x;
    const int tr = tid >> 4;   // 0..15
    const int tc = tid & 15;   // 0..15

    float* __restrict__ Ab = g_A + (size_t)z * Sq * Sq;

    if (blockIdx.x > blockIdx.y) {
        float4 zero4 = make_float4(0.f, 0.f, 0.f, 0.f);
        #pragma unroll
        for (int i = 0; i < 4; i++) {
            int gi = i0 + tr * 4 + i;
            *(float4*)&Ab[(size_t)gi * Sq + j0 + tc * 4] = zero4;
        }
        return;
    }

    const float* __restrict__ Qb = g_Q + (size_t)z * Sq * Dh;
    const float* __restrict__ Kb = g_K + (size_t)z * Sq * Dh;

    __shared__ float Qs[32][65];
    __shared__ float Ks[32][65];

    float acc[4][4];
    #pragma unroll
    for (int i = 0; i < 4; i++)
        #pragma unroll
        for (int j = 0; j < 4; j++) acc[i][j] = 0.0f;

    for (int k0 = 0; k0 < Dh; k0 += 32) {
        #pragma unroll
        for (int t = 0; t < 2; t++) {
            int idx = tid + t * 256;
            int r  = idx >> 3;            // 0..63
            int c4 = (idx & 7) << 2;      // 0..28
            float4 qv = *(const float4*)(Qb + (size_t)(i0 + r) * Dh + k0 + c4);
            Qs[c4 + 0][r] = qv.x; Qs[c4 + 1][r] = qv.y;
            Qs[c4 + 2][r] = qv.z; Qs[c4 + 3][r] = qv.w;
            float4 kv = *(const float4*)(Kb + (size_t)(j0 + r) * Dh + k0 + c4);
            Ks[c4 + 0][r] = kv.x; Ks[c4 + 1][r] = kv.y;
            Ks[c4 + 2][r] = kv.z; Ks[c4 + 3][r] = kv.w;
        }
        __syncthreads();
        #pragma unroll
        for (int kk = 0; kk < 32; kk++) {
            float rq[4], rk[4];
            #pragma unroll
            for (int i = 0; i < 4; i++) rq[i] = Qs[kk][tr * 4 + i];
            #pragma unroll
            for (int j = 0; j < 4; j++) rk[j] = Ks[kk][tc * 4 + j];
            #pragma unroll
            for (int i = 0; i < 4; i++)
                #pragma unroll
                for (int j = 0; j < 4; j++)
                    acc[i][j] = fmaf(rq[i], rk[j], acc[i][j]);
        }
        __syncthreads();
    }

    const float rscale = 1.0f / sqrtf((float)Im);   // 1/sqrt(1536)
    #pragma unroll
    for (int i = 0; i < 4; i++) {
        int gi = i0 + tr * 4 + i;
        #pragma unroll
        for (int j = 0; j < 4; j++) {
            int gj = j0 + tc * 4 + j;
            float v = 0.0f;
            if (gj <= gi) {
                float s = acc[i][j] * rscale + g_bias[gi - gj];
                v = (s > 0.0f) ? s * s : 0.0f;
            }
            Ab[(size_t)gi * Sq + gj] = v;
        }
    }
}

// ---------------------------------------------------------------------------
// O[b] = (A[b] @ V[b]) * G[b].   Causal: k-loop limited to rowBlock+128.
// ---------------------------------------------------------------------------
__global__ void __launch_bounds__(NT)
gemm_av_gate_kernel()
{
    const int z = blockIdx.z;
    const float* __restrict__ A = g_A + (size_t)z * Sq * Sq;
    const float* __restrict__ V = g_V + (size_t)z * Sq * Im;

    float acc[TM][TN];
    #pragma unroll
    for (int i = 0; i < TM; i++)
        #pragma unroll
        for (int j = 0; j < TN; j++) acc[i][j] = 0.0f;

    const int kEnd = blockIdx.y * BM + BM;   // causal limit (multiple of 8)
    run_sgemm(A, Sq, V, Im, 0, kEnd, acc);

    const int tid = threadIdx.x;
    const int row0 = blockIdx.y * BM + (tid >> 4) * TM;   // within batch
    const int col0 = blockIdx.x * BN + (tid & 15) * TN;
    #pragma unroll
    for (int i = 0; i < TM; i++)
        #pragma unroll
        for (int j = 0; j < TN; j++) {
            size_t idx = (size_t)(z * Sq + row0 + i) * Im + col0 + j;
            g_O[idx] = acc[i][j] * g_G[idx];
        }
}

// ---------------------------------------------------------------------------
// out = O @ out_W + out_b.   O:(8192,1536)  out_W:(1536,768)
// ---------------------------------------------------------------------------
__global__ void __launch_bounds__(NT)
gemm_out_kernel(const float* __restrict__ W, const float* __restrict__ bias,
                float* __restrict__ out)
{
    float acc[TM][TN];
    #pragma unroll
    for (int i = 0; i < TM; i++)
        #pragma unroll
        for (int j = 0; j < TN; j++) acc[i][j] = 0.0f;

    run_sgemm(g_O, Im, W, Dm, 0, Im, acc);

    const int tid = threadIdx.x;
    const int row0 = blockIdx.y * BM + (tid >> 4) * TM;
    const int col0 = blockIdx.x * BN + (tid & 15) * TN;
    #pragma unroll
    for (int i = 0; i < TM; i++)
        #pragma unroll
        for (int j = 0; j < TN; j++)
            out[(size_t)(row0 + i) * Dm + col0 + j] = acc[i][j] + bias[col0 + j];
}

// ---------------------------------------------------------------------------
// Launch.  Input order detected at runtime from in_sizes[0] (element counts):
//   6291456 -> dict/signature order (x first)
//   1179648 -> alphabetical key order (g_W first)
// ---------------------------------------------------------------------------
extern "C" void kernel_launch(void* const* d_in, const int* in_sizes, int n_in,
                              void* d_out, int out_size)
{
    const float *x, *vW, *vb, *gW, *gb, *inW, *inb;
    const float *qg, *qb, *kg, *kb, *oW, *ob, *rel;

    if (in_sizes[0] == Bsz * Sq * Dm) {
        // dict / reference-signature order
        x   = (const float*)d_in[0];
        vW  = (const float*)d_in[1];
        vb  = (const float*)d_in[2];
        gW  = (const float*)d_in[3];
        gb  = (const float*)d_in[4];
        inW = (const float*)d_in[5];
        inb = (const float*)d_in[6];
        qg  = (const float*)d_in[7];
        qb  = (const float*)d_in[8];
        kg  = (const float*)d_in[9];
        kb  = (const float*)d_in[10];
        oW  = (const float*)d_in[11];
        ob  = (const float*)d_in[12];
        rel = (const float*)d_in[13];
    } else {
        // alphabetical key order
        gW  = (const float*)d_in[0];
        gb  = (const float*)d_in[1];
        inW = (const float*)d_in[2];
        inb = (const float*)d_in[3];
        kb  = (const float*)d_in[4];   // k_beta
        kg  = (const float*)d_in[5];   // k_gamma
        oW  = (const float*)d_in[6];
        ob  = (const float*)d_in[7];
        qb  = (const float*)d_in[8];   // q_beta
        qg  = (const float*)d_in[9];   // q_gamma
        rel = (const float*)d_in[10];
        vW  = (const float*)d_in[11];
        vb  = (const float*)d_in[12];
        x   = (const float*)d_in[13];
    }

    float* out = (float*)d_out;

    bias_init_kernel<<<(Sq + 255) / 256, 256>>>(rel);

    dim3 blk(NT);
    gemm_silu_kernel<<<dim3(Im / BN, Mtot / BM), blk>>>(x, vW, vb, /*which=*/0);
    gemm_silu_kernel<<<dim3(Im / BN, Mtot / BM), blk>>>(x, gW, gb, /*which=*/1);
    gemm_qk_kernel  <<<dim3(1,       Mtot / BM), blk>>>(x, inW, inb, qg, qb, kg, kb);
    scores_kernel   <<<dim3(Sq / 64, Sq / 64, Bsz), blk>>>();
    gemm_av_gate_kernel<<<dim3(Im / BN, Sq / BM, Bsz), blk>>>();
    gemm_out_kernel <<<dim3(Dm / BN, Mtot / BM), blk>>>(oW, ob, out);
}

// round 6
// speedup vs baseline: 2.5646x; 2.5646x over previous
#include <cuda_runtime.h>
#include <math.h>
#include <stdint.h>

// Problem constants
#define Bsz 4
#define Sq  2048
#define Dm  768
#define Im  1536
#define Dh  128
#define Mtot (Bsz*Sq)   // 8192

#define BM 128
#define BN 128
#define BKM 16
#define NT 256

// Scratch (device globals; no allocations allowed)
__device__ float g_V[Mtot*Im];
__device__ float g_G[Mtot*Im];
__device__ float g_Q[Mtot*Dh];
__device__ float g_K[Mtot*Dh];
__device__ float g_A[Bsz*Sq*Sq];
__device__ float g_O[Mtot*Im];
__device__ float g_bias[Sq];

// ---------------------------------------------------------------------------
// Relative-position bias LUT
// ---------------------------------------------------------------------------
__global__ void bias_init_kernel(const float* __restrict__ rel_emb)
{
    int d = blockIdx.x * blockDim.x + threadIdx.x;
    if (d >= Sq) return;
    int bucket;
    if (d < 16) {
        bucket = d;
    } else {
        int v = 16 + (int)(log((double)d / 16.0) / log(8.0) * 16.0);
        bucket = v < 31 ? v : 31;
    }
    g_bias[d] = rel_emb[bucket] * sqrtf((float)Dh);
}

// ---------------------------------------------------------------------------
// tf32 helpers
// ---------------------------------------------------------------------------
__device__ __forceinline__ uint32_t f2tf(float x)
{
    uint32_t r;
    asm("cvt.rna.tf32.f32 %0, %1;" : "=r"(r) : "f"(x));
    return r;
}

__device__ __forceinline__ void mma8(float (&d)[4], const uint32_t (&a)[4],
                                     const uint32_t (&b)[2])
{
    asm volatile(
        "mma.sync.aligned.m16n8k8.row.col.f32.tf32.tf32.f32 "
        "{%0,%1,%2,%3}, {%4,%5,%6,%7}, {%8,%9}, {%0,%1,%2,%3};"
        : "+f"(d[0]), "+f"(d[1]), "+f"(d[2]), "+f"(d[3])
        : "r"(a[0]), "r"(a[1]), "r"(a[2]), "r"(a[3]), "r"(b[0]), "r"(b[1]));
}

// ---------------------------------------------------------------------------
// Tensor-core GEMM core: 128x128 CTA tile, 8 warps of 64x32, tf32 m16n8k8.
// A: row-major (M x K).  B: if !TRANSB, B[k][n] (K x N); if TRANSB, B[n][k].
// acc[mt][nt][4] per-thread fragments.
// ---------------------------------------------------------------------------
template<bool TRANSB>
__device__ __forceinline__ void run_mma(
    const float* __restrict__ A, int lda, int rowBase,
    const float* __restrict__ B, int ldb, int colBase,
    int kStart, int kEnd, float (&acc)[4][4][4])
{
    __shared__ uint32_t As[BKM][BM + 8];
    __shared__ uint32_t Bs[BKM][BN + 8];
    const int tid  = threadIdx.x;
    const int lane = tid & 31;
    const int warp = tid >> 5;
    const int m0w  = (warp >> 2) * 64;
    const int n0w  = (warp & 3) * 32;
    const int lq   = lane >> 2;   // 0..7
    const int lr   = lane & 3;    // 0..3

    const int aRow = tid >> 1;            // 0..127
    const int aCol = (tid & 1) << 3;      // 0 or 8

    for (int k0 = kStart; k0 < kEnd; k0 += BKM) {
        // --- A tile: global (row-major) -> As[k][m] (tf32 bits) ---
        {
            const float* p = A + (size_t)(rowBase + aRow) * lda + k0 + aCol;
            float4 v0 = *(const float4*)(p);
            float4 v1 = *(const float4*)(p + 4);
            As[aCol + 0][aRow] = f2tf(v0.x); As[aCol + 1][aRow] = f2tf(v0.y);
            As[aCol + 2][aRow] = f2tf(v0.z); As[aCol + 3][aRow] = f2tf(v0.w);
            As[aCol + 4][aRow] = f2tf(v1.x); As[aCol + 5][aRow] = f2tf(v1.y);
            As[aCol + 6][aRow] = f2tf(v1.z); As[aCol + 7][aRow] = f2tf(v1.w);
        }
        // --- B tile -> Bs[k][n] ---
        if (!TRANSB) {
            const int bRow = tid >> 4;            // 0..15
            const int bCol = (tid & 15) << 3;     // 0..120
            const float* p = B + (size_t)(k0 + bRow) * ldb + colBase + bCol;
            float4 v0 = *(const float4*)(p);
            float4 v1 = *(const float4*)(p + 4);
            uint4 w0 = make_uint4(f2tf(v0.x), f2tf(v0.y), f2tf(v0.z), f2tf(v0.w));
            uint4 w1 = make_uint4(f2tf(v1.x), f2tf(v1.y), f2tf(v1.z), f2tf(v1.w));
            *(uint4*)&Bs[bRow][bCol]     = w0;
            *(uint4*)&Bs[bRow][bCol + 4] = w1;
        } else {
            const int bn = tid >> 1;              // 0..127 (n index)
            const int bk = (tid & 1) << 3;        // 0 or 8
            const float* p = B + (size_t)(colBase + bn) * ldb + k0 + bk;
            float4 v0 = *(const float4*)(p);
            float4 v1 = *(const float4*)(p + 4);
            Bs[bk + 0][bn] = f2tf(v0.x); Bs[bk + 1][bn] = f2tf(v0.y);
            Bs[bk + 2][bn] = f2tf(v0.z); Bs[bk + 3][bn] = f2tf(v0.w);
            Bs[bk + 4][bn] = f2tf(v1.x); Bs[bk + 5][bn] = f2tf(v1.y);
            Bs[bk + 6][bn] = f2tf(v1.z); Bs[bk + 7][bn] = f2tf(v1.w);
        }
        __syncthreads();

        #pragma unroll
        for (int ks = 0; ks < BKM; ks += 8) {
            uint32_t af[4][4], bf[4][2];
            #pragma unroll
            for (int mt = 0; mt < 4; mt++) {
                int m = m0w + mt * 16 + lq;
                af[mt][0] = As[ks + lr][m];
                af[mt][1] = As[ks + lr][m + 8];
                af[mt][2] = As[ks + lr + 4][m];
                af[mt][3] = As[ks + lr + 4][m + 8];
            }
            #pragma unroll
            for (int nt = 0; nt < 4; nt++) {
                int n = n0w + nt * 8 + lq;
                bf[nt][0] = Bs[ks + lr][n];
                bf[nt][1] = Bs[ks + lr + 4][n];
            }
            #pragma unroll
            for (int mt = 0; mt < 4; mt++)
                #pragma unroll
                for (int nt = 0; nt < 4; nt++)
                    mma8(acc[mt][nt], af[mt], bf[nt]);
        }
        __syncthreads();
    }
}

#define ACC_INIT(acc)                                   \
    _Pragma("unroll")                                   \
    for (int mt = 0; mt < 4; mt++)                      \
        _Pragma("unroll")                               \
        for (int nt = 0; nt < 4; nt++)                  \
            _Pragma("unroll")                           \
            for (int e = 0; e < 4; e++) acc[mt][nt][e] = 0.0f;

// Epilogue index helpers: element (mt, nt, half, j) lives at
//   row = rowBase + (warp>>2)*64 + mt*16 + (lane>>2) + half*8
//   col = colBase + (warp&3)*32 + nt*8 + (lane&3)*2 + j
#define EPI_PREAMBLE                                       \
    const int tid  = threadIdx.x;                          \
    const int lane = tid & 31;                             \
    const int warp = tid >> 5;                             \
    const int mBase = (warp >> 2) * 64 + (lane >> 2);      \
    const int nBase = (warp & 3) * 32 + (lane & 3) * 2;

__device__ __forceinline__ float silu_f(float x)
{
    return x / (1.0f + __expf(-x));
}

// ---------------------------------------------------------------------------
// C = silu(X @ W + b)   for V (which=0) and G (which=1)
// ---------------------------------------------------------------------------
__global__ void __launch_bounds__(NT, 2)
gemm_silu_kernel(const float* __restrict__ X, const float* __restrict__ W,
                 const float* __restrict__ bias, int which)
{
    float* __restrict__ C = which ? g_G : g_V;
    float acc[4][4][4];
    ACC_INIT(acc);
    run_mma<false>(X, Dm, blockIdx.y * BM, W, Im, blockIdx.x * BN, 0, Dm, acc);

    EPI_PREAMBLE;
    const int row0 = blockIdx.y * BM + mBase;
    const int col0 = blockIdx.x * BN + nBase;
    #pragma unroll
    for (int mt = 0; mt < 4; mt++)
        #pragma unroll
        for (int nt = 0; nt < 4; nt++) {
            int c = col0 + nt * 8;
            float b0 = bias[c], b1 = bias[c + 1];
            #pragma unroll
            for (int h = 0; h < 2; h++) {
                int r = row0 + mt * 16 + h * 8;
                float2 o;
                o.x = silu_f(acc[mt][nt][2 * h + 0] + b0);
                o.y = silu_f(acc[mt][nt][2 * h + 1] + b1);
                *(float2*)&C[(size_t)r * Im + c] = o;
            }
        }
}

// ---------------------------------------------------------------------------
// base = silu(X @ inW + inb);  Q = base*qg+qb;  K = base*kg+kb
// ---------------------------------------------------------------------------
__global__ void __launch_bounds__(NT, 2)
gemm_qk_kernel(const float* __restrict__ X, const float* __restrict__ W,
               const float* __restrict__ inb,
               const float* __restrict__ qg, const float* __restrict__ qb,
               const float* __restrict__ kg, const float* __restrict__ kb)
{
    float acc[4][4][4];
    ACC_INIT(acc);
    run_mma<false>(X, Dm, blockIdx.y * BM, W, Dh, 0, 0, Dm, acc);

    EPI_PREAMBLE;
    const int row0 = blockIdx.y * BM + mBase;
    #pragma unroll
    for (int mt = 0; mt < 4; mt++)
        #pragma unroll
        for (int nt = 0; nt < 4; nt++) {
            int c = nBase + nt * 8;
            #pragma unroll
            for (int h = 0; h < 2; h++) {
                int r = row0 + mt * 16 + h * 8;
                #pragma unroll
                for (int j = 0; j < 2; j++) {
                    int cc = c + j;
                    float base = silu_f(acc[mt][nt][2 * h + j] + inb[cc]);
                    size_t idx = (size_t)r * Dh + cc;
                    g_Q[idx] = base * qg[cc] + qb[cc];
                    g_K[idx] = base * kg[cc] + kb[cc];
                }
            }
        }
}

// ---------------------------------------------------------------------------
// A[b] = relu(Q K^T / sqrt(1536) + bias)^2, causal.  128x128 tiles.
// ---------------------------------------------------------------------------
__global__ void __launch_bounds__(NT, 2)
scores_kernel()
{
    const int z  = blockIdx.z;
    const int i0 = blockIdx.y * BM;
    const int j0 = blockIdx.x * BN;
    float* __restrict__ Ab = g_A + (size_t)z * Sq * Sq;

    if (blockIdx.x > blockIdx.y) {
        // fully masked: zero-fill 128x128 with uint4 stores
        const int tid = threadIdx.x;
        uint4 zz = make_uint4(0, 0, 0, 0);
        #pragma unroll
        for (int t = 0; t < 16; t++) {
            int idx = tid + t * NT;           // 0..4095, covers 128*32 float4
            int r  = idx >> 5;                // 0..127
            int c4 = (idx & 31) << 2;         // 0..124
            *(uint4*)&Ab[(size_t)(i0 + r) * Sq + j0 + c4] = zz;
        }
        return;
    }

    const float* __restrict__ Qb = g_Q + (size_t)z * Sq * Dh;
    const float* __restrict__ Kb = g_K + (size_t)z * Sq * Dh;

    float acc[4][4][4];
    ACC_INIT(acc);
    run_mma<true>(Qb, Dh, i0, Kb, Dh, j0, 0, Dh, acc);

    EPI_PREAMBLE;
    const float rscale = 1.0f / sqrtf((float)Im);
    const int gi0 = i0 + mBase;
    const int gj0 = j0 + nBase;
    #pragma unroll
    for (int mt = 0; mt < 4; mt++)
        #pragma unroll
        for (int nt = 0; nt < 4; nt++) {
            #pragma unroll
            for (int h = 0; h < 2; h++) {
                int gi = gi0 + mt * 16 + h * 8;
                int gj = gj0 + nt * 8;
                float2 o;
                float v0 = 0.0f, v1 = 0.0f;
                if (gj <= gi) {
                    float s = acc[mt][nt][2 * h] * rscale + g_bias[gi - gj];
                    v0 = (s > 0.0f) ? s * s : 0.0f;
                }
                if (gj + 1 <= gi) {
                    float s = acc[mt][nt][2 * h + 1] * rscale + g_bias[gi - gj - 1];
                    v1 = (s > 0.0f) ? s * s : 0.0f;
                }
                o.x = v0; o.y = v1;
                *(float2*)&Ab[(size_t)gi * Sq + gj] = o;
            }
        }
}

// ---------------------------------------------------------------------------
// O[b] = (A[b] @ V[b]) * G[b].   Causal: k-loop limited to rowBlock+128.
// ---------------------------------------------------------------------------
__global__ void __launch_bounds__(NT, 2)
gemm_av_gate_kernel()
{
    const int z = blockIdx.z;
    const float* __restrict__ A = g_A + (size_t)z * Sq * Sq;
    const float* __restrict__ V = g_V + (size_t)z * Sq * Im;

    float acc[4][4][4];
    ACC_INIT(acc);
    const int kEnd = blockIdx.y * BM + BM;
    run_mma<false>(A, Sq, blockIdx.y * BM, V, Im, blockIdx.x * BN, 0, kEnd, acc);

    EPI_PREAMBLE;
    const int row0 = z * Sq + blockIdx.y * BM + mBase;
    const int col0 = blockIdx.x * BN + nBase;
    #pragma unroll
    for (int mt = 0; mt < 4; mt++)
        #pragma unroll
        for (int nt = 0; nt < 4; nt++) {
            int c = col0 + nt * 8;
            #pragma unroll
            for (int h = 0; h < 2; h++) {
                int r = row0 + mt * 16 + h * 8;
                size_t idx = (size_t)r * Im + c;
                float2 g = *(const float2*)&g_G[idx];
                float2 o;
                o.x = acc[mt][nt][2 * h + 0] * g.x;
                o.y = acc[mt][nt][2 * h + 1] * g.y;
                *(float2*)&g_O[idx] = o;
            }
        }
}

// ---------------------------------------------------------------------------
// out = O @ out_W + out_b
// ---------------------------------------------------------------------------
__global__ void __launch_bounds__(NT, 2)
gemm_out_kernel(const float* __restrict__ W, const float* __restrict__ bias,
                float* __restrict__ out)
{
    float acc[4][4][4];
    ACC_INIT(acc);
    run_mma<false>(g_O, Im, blockIdx.y * BM, W, Dm, blockIdx.x * BN, 0, Im, acc);

    EPI_PREAMBLE;
    const int row0 = blockIdx.y * BM + mBase;
    const int col0 = blockIdx.x * BN + nBase;
    #pragma unroll
    for (int mt = 0; mt < 4; mt++)
        #pragma unroll
        for (int nt = 0; nt < 4; nt++) {
            int c = col0 + nt * 8;
            float b0 = bias[c], b1 = bias[c + 1];
            #pragma unroll
            for (int h = 0; h < 2; h++) {
                int r = row0 + mt * 16 + h * 8;
                float2 o;
                o.x = acc[mt][nt][2 * h + 0] + b0;
                o.y = acc[mt][nt][2 * h + 1] + b1;
                *(float2*)&out[(size_t)r * Dm + c] = o;
            }
        }
}

// ---------------------------------------------------------------------------
// Launch (input order auto-detected from in_sizes[0])
// ---------------------------------------------------------------------------
extern "C" void kernel_launch(void* const* d_in, const int* in_sizes, int n_in,
                              void* d_out, int out_size)
{
    const float *x, *vW, *vb, *gW, *gb, *inW, *inb;
    const float *qg, *qb, *kg, *kb, *oW, *ob, *rel;

    if (in_sizes[0] == Bsz * Sq * Dm) {
        x   = (const float*)d_in[0];
        vW  = (const float*)d_in[1];
        vb  = (const float*)d_in[2];
        gW  = (const float*)d_in[3];
        gb  = (const float*)d_in[4];
        inW = (const float*)d_in[5];
        inb = (const float*)d_in[6];
        qg  = (const float*)d_in[7];
        qb  = (const float*)d_in[8];
        kg  = (const float*)d_in[9];
        kb  = (const float*)d_in[10];
        oW  = (const float*)d_in[11];
        ob  = (const float*)d_in[12];
        rel = (const float*)d_in[13];
    } else {
        gW  = (const float*)d_in[0];
        gb  = (const float*)d_in[1];
        inW = (const float*)d_in[2];
        inb = (const float*)d_in[3];
        kb  = (const float*)d_in[4];
        kg  = (const float*)d_in[5];
        oW  = (const float*)d_in[6];
        ob  = (const float*)d_in[7];
        qb  = (const float*)d_in[8];
        qg  = (const float*)d_in[9];
        rel = (const float*)d_in[10];
        vW  = (const float*)d_in[11];
        vb  = (const float*)d_in[12];
        x   = (const float*)d_in[13];
    }

    float* out = (float*)d_out;

    bias_init_kernel<<<(Sq + 255) / 256, 256>>>(rel);

    dim3 blk(NT);
    gemm_silu_kernel<<<dim3(Im / BN, Mtot / BM), blk>>>(x, vW, vb, 0);
    gemm_silu_kernel<<<dim3(Im / BN, Mtot / BM), blk>>>(x, gW, gb, 1);
    gemm_qk_kernel  <<<dim3(1,       Mtot / BM), blk>>>(x, inW, inb, qg, qb, kg, kb);
    scores_kernel   <<<dim3(Sq / BN, Sq / BM, Bsz), blk>>>();
    gemm_av_gate_kernel<<<dim3(Im / BN, Sq / BM, Bsz), blk>>>();
    gemm_out_kernel <<<dim3(Dm / BN, Mtot / BM), blk>>>(oW, ob, out);
}

// round 7
// speedup vs baseline: 3.1068x; 1.2114x over previous
#include <cuda_runtime.h>
#include <math.h>
#include <stdint.h>

// Problem constants
#define Bsz 4
#define Sq  2048
#define Dm  768
#define Im  1536
#define Dh  128
#define Mtot (Bsz*Sq)   // 8192

#define BM 128
#define BN 128
#define BK 16
#define NT 256
#define STAGES 3

// Scratch (device globals; no allocations allowed)
__device__ float g_V[Mtot*Im];
__device__ float g_G[Mtot*Im];
__device__ float g_Q[Mtot*Dh];
__device__ float g_K[Mtot*Dh];
__device__ float g_A[Bsz*Sq*Sq];
__device__ float g_O[Mtot*Im];
__device__ float g_bias[Sq];

// smem geometry (in floats)
#define A_ST   20            // A tile row stride: 16 + 4 pad (conflict-free)
#define A_SZ   (BM*A_ST)     // 2560 floats / stage
#define BT_ST  20            // B-transposed row stride
#define BT_SZ  (BN*BT_ST)    // 2560 floats / stage
#define BN_ST  136           // B-normal row stride: 128 + 8 pad
#define BN_SZ  (BK*BN_ST)    // 2176 floats / stage

#define SMEM_BYTES_N  (STAGES*(A_SZ + BN_SZ)*4)   // 56832
#define SMEM_BYTES_T  (STAGES*(A_SZ + BT_SZ)*4)   // 61440

// ---------------------------------------------------------------------------
// Relative-position bias LUT
// ---------------------------------------------------------------------------
__global__ void bias_init_kernel(const float* __restrict__ rel_emb)
{
    int d = blockIdx.x * blockDim.x + threadIdx.x;
    if (d >= Sq) return;
    int bucket;
    if (d < 16) {
        bucket = d;
    } else {
        int v = 16 + (int)(log((double)d / 16.0) / log(8.0) * 16.0);
        bucket = v < 31 ? v : 31;
    }
    g_bias[d] = rel_emb[bucket] * sqrtf((float)Dh);
}

// ---------------------------------------------------------------------------
// helpers
// ---------------------------------------------------------------------------
__device__ __forceinline__ uint32_t f2tf(float x)
{
    uint32_t r;
    asm("cvt.rna.tf32.f32 %0, %1;" : "=r"(r) : "f"(x));
    return r;
}

__device__ __forceinline__ void cp16(uint32_t dst, const float* src)
{
    asm volatile("cp.async.cg.shared.global [%0], [%1], 16;"
                 :: "r"(dst), "l"(src));
}

__device__ __forceinline__ void mma8(float (&d)[4], const uint32_t (&a)[4],
                                     const uint32_t (&b)[2])
{
    asm volatile(
        "mma.sync.aligned.m16n8k8.row.col.f32.tf32.tf32.f32 "
        "{%0,%1,%2,%3}, {%4,%5,%6,%7}, {%8,%9}, {%0,%1,%2,%3};"
        : "+f"(d[0]), "+f"(d[1]), "+f"(d[2]), "+f"(d[3])
        : "r"(a[0]), "r"(a[1]), "r"(a[2]), "r"(a[3]), "r"(b[0]), "r"(b[1]));
}

extern __shared__ __align__(16) float sm_dyn[];

// ---------------------------------------------------------------------------
// Pipelined tensor-core GEMM core: 128x128 CTA tile, 8 warps of 64x32,
// tf32 m16n8k8, 3-stage cp.async, fp32 in smem, cvt at fragment load.
// A: row-major (M x K). B: !TRANSB -> B[k][n]; TRANSB -> B[n][k].
// ---------------------------------------------------------------------------
template<bool TRANSB>
__device__ __forceinline__ void run_mma(
    const float* __restrict__ A, int lda, int rowBase,
    const float* __restrict__ B, int ldb, int colBase,
    int kEnd, float (&acc)[4][4][4])
{
    constexpr int B_SZ = TRANSB ? BT_SZ : BN_SZ;

    float* As = sm_dyn;
    float* Bs = sm_dyn + STAGES * A_SZ;

    const int tid  = threadIdx.x;
    const int lane = tid & 31;
    const int warp = tid >> 5;
    const int m0w  = (warp >> 2) * 64;
    const int n0w  = (warp & 3) * 32;
    const int lq   = lane >> 2;
    const int lr   = lane & 3;

    const int ktiles = kEnd / BK;

    // A cp.async mapping: row = tid>>1, 8 floats at kc = (tid&1)*8
    const int aRow = tid >> 1;
    const int aKc  = (tid & 1) << 3;
    const float* aSrc = A + (size_t)(rowBase + aRow) * lda + aKc;
    const uint32_t aDst0 = (uint32_t)__cvta_generic_to_shared(As)
                           + (uint32_t)(aRow * A_ST + aKc) * 4u;

    // B cp.async mapping
    const float* bSrcT = nullptr;
    uint32_t bDst0 = (uint32_t)__cvta_generic_to_shared(Bs);
    int bK0 = 0, bN0 = 0, bK1 = 0, bN1 = 0;
    if (TRANSB) {
        bSrcT = B + (size_t)(colBase + aRow) * ldb + aKc;    // row n, 8 floats
        bDst0 += (uint32_t)(aRow * BT_ST + aKc) * 4u;
    } else {
        int c0 = tid, c1 = tid + 256;
        bK0 = c0 >> 5; bN0 = (c0 & 31) << 2;
        bK1 = c1 >> 5; bN1 = (c1 & 31) << 2;
    }

    #define LOAD_TILE(kt, slot)                                               \
    do {                                                                      \
        const float* as_ = aSrc + (kt) * BK;                                  \
        uint32_t ad_ = aDst0 + (uint32_t)((slot) * A_SZ) * 4u;                \
        cp16(ad_, as_); cp16(ad_ + 16u, as_ + 4);                             \
        if (TRANSB) {                                                         \
            const float* bs_ = bSrcT + (kt) * BK;                             \
            uint32_t bd_ = bDst0 + (uint32_t)((slot) * B_SZ) * 4u;            \
            cp16(bd_, bs_); cp16(bd_ + 16u, bs_ + 4);                         \
        } else {                                                              \
            uint32_t bd_ = bDst0 + (uint32_t)((slot) * B_SZ) * 4u;            \
            const float* b0_ = B + (size_t)((kt) * BK + bK0) * ldb + colBase + bN0; \
            const float* b1_ = B + (size_t)((kt) * BK + bK1) * ldb + colBase + bN1; \
            cp16(bd_ + (uint32_t)(bK0 * BN_ST + bN0) * 4u, b0_);              \
            cp16(bd_ + (uint32_t)(bK1 * BN_ST + bN1) * 4u, b1_);              \
        }                                                                     \
    } while (0)

    // prologue: stages 0..STAGES-2   (ktiles >= 8 always here)
    LOAD_TILE(0, 0);
    asm volatile("cp.async.commit_group;");
    LOAD_TILE(1, 1);
    asm volatile("cp.async.commit_group;");

    int slot = 0;
    for (int kt = 0; kt < ktiles; kt++) {
        asm volatile("cp.async.wait_group 1;");
        __syncthreads();

        int nkt = kt + STAGES - 1;
        if (nkt < ktiles) {
            int nslot = slot + STAGES - 1;
            if (nslot >= STAGES) nslot -= STAGES;
            LOAD_TILE(nkt, nslot);
        }
        asm volatile("cp.async.commit_group;");

        const float* Asl = As + slot * A_SZ;
        const float* Bsl = Bs + slot * B_SZ;

        #pragma unroll
        for (int ks = 0; ks < BK; ks += 8) {
            uint32_t af[4][4], bf[4][2];
            #pragma unroll
            for (int mt = 0; mt < 4; mt++) {
                int m = m0w + mt * 16 + lq;
                int k = ks + lr;
                af[mt][0] = f2tf(Asl[m * A_ST + k]);
                af[mt][1] = f2tf(Asl[(m + 8) * A_ST + k]);
                af[mt][2] = f2tf(Asl[m * A_ST + k + 4]);
                af[mt][3] = f2tf(Asl[(m + 8) * A_ST + k + 4]);
            }
            #pragma unroll
            for (int nt = 0; nt < 4; nt++) {
                int n = n0w + nt * 8 + lq;
                int k = ks + lr;
                if (TRANSB) {
                    bf[nt][0] = f2tf(Bsl[n * BT_ST + k]);
                    bf[nt][1] = f2tf(Bsl[n * BT_ST + k + 4]);
                } else {
                    bf[nt][0] = f2tf(Bsl[k * BN_ST + n]);
                    bf[nt][1] = f2tf(Bsl[(k + 4) * BN_ST + n]);
                }
            }
            #pragma unroll
            for (int mt = 0; mt < 4; mt++)
                #pragma unroll
                for (int nt = 0; nt < 4; nt++)
                    mma8(acc[mt][nt], af[mt], bf[nt]);
        }

        if (++slot == STAGES) slot = 0;
    }
    #undef LOAD_TILE
}

#define ACC_INIT(acc)                                   \
    _Pragma("unroll")                                   \
    for (int mt = 0; mt < 4; mt++)                      \
        _Pragma("unroll")                               \
        for (int nt = 0; nt < 4; nt++)                  \
            _Pragma("unroll")                           \
            for (int e = 0; e < 4; e++) acc[mt][nt][e] = 0.0f;

#define EPI_PREAMBLE                                       \
    const int tid  = threadIdx.x;                          \
    const int lane = tid & 31;                             \
    const int warp = tid >> 5;                             \
    const int mBase = (warp >> 2) * 64 + (lane >> 2);      \
    const int nBase = (warp & 3) * 32 + (lane & 3) * 2;

__device__ __forceinline__ float silu_f(float x)
{
    return x / (1.0f + __expf(-x));
}

// ---------------------------------------------------------------------------
// C = silu(X @ W + b)   for V (which=0) and G (which=1)
// ---------------------------------------------------------------------------
__global__ void __launch_bounds__(NT, 2)
gemm_silu_kernel(const float* __restrict__ X, const float* __restrict__ W,
                 const float* __restrict__ bias, int which)
{
    float* __restrict__ C = which ? g_G : g_V;
    float acc[4][4][4];
    ACC_INIT(acc);
    run_mma<false>(X, Dm, blockIdx.y * BM, W, Im, blockIdx.x * BN, Dm, acc);

    EPI_PREAMBLE;
    const int row0 = blockIdx.y * BM + mBase;
    const int col0 = blockIdx.x * BN + nBase;
    #pragma unroll
    for (int mt = 0; mt < 4; mt++)
        #pragma unroll
        for (int nt = 0; nt < 4; nt++) {
            int c = col0 + nt * 8;
            float b0 = bias[c], b1 = bias[c + 1];
            #pragma unroll
            for (int h = 0; h < 2; h++) {
                int r = row0 + mt * 16 + h * 8;
                float2 o;
                o.x = silu_f(acc[mt][nt][2 * h + 0] + b0);
                o.y = silu_f(acc[mt][nt][2 * h + 1] + b1);
                *(float2*)&C[(size_t)r * Im + c] = o;
            }
        }
}

// ---------------------------------------------------------------------------
// base = silu(X @ inW + inb);  Q = base*qg+qb;  K = base*kg+kb
// ---------------------------------------------------------------------------
__global__ void __launch_bounds__(NT, 2)
gemm_qk_kernel(const float* __restrict__ X, const float* __restrict__ W,
               const float* __restrict__ inb,
               const float* __restrict__ qg, const float* __restrict__ qb,
               const float* __restrict__ kg, const float* __restrict__ kb)
{
    float acc[4][4][4];
    ACC_INIT(acc);
    run_mma<false>(X, Dm, blockIdx.y * BM, W, Dh, 0, Dm, acc);

    EPI_PREAMBLE;
    const int row0 = blockIdx.y * BM + mBase;
    #pragma unroll
    for (int mt = 0; mt < 4; mt++)
        #pragma unroll
        for (int nt = 0; nt < 4; nt++) {
            int c = nBase + nt * 8;
            #pragma unroll
            for (int h = 0; h < 2; h++) {
                int r = row0 + mt * 16 + h * 8;
                #pragma unroll
                for (int j = 0; j < 2; j++) {
                    int cc = c + j;
                    float base = silu_f(acc[mt][nt][2 * h + j] + inb[cc]);
                    size_t idx = (size_t)r * Dh + cc;
                    g_Q[idx] = base * qg[cc] + qb[cc];
                    g_K[idx] = base * kg[cc] + kb[cc];
                }
            }
        }
}

// ---------------------------------------------------------------------------
// A[b] = relu(Q K^T / sqrt(1536) + bias)^2, causal.  128x128 tiles.
// ---------------------------------------------------------------------------
__global__ void __launch_bounds__(NT, 2)
scores_kernel()
{
    const int z  = blockIdx.z;
    const int i0 = blockIdx.y * BM;
    const int j0 = blockIdx.x * BN;
    float* __restrict__ Ab = g_A + (size_t)z * Sq * Sq;

    if (blockIdx.x > blockIdx.y) {
        const int tid = threadIdx.x;
        uint4 zz = make_uint4(0, 0, 0, 0);
        #pragma unroll
        for (int t = 0; t < 16; t++) {
            int idx = tid + t * NT;
            int r  = idx >> 5;
            int c4 = (idx & 31) << 2;
            *(uint4*)&Ab[(size_t)(i0 + r) * Sq + j0 + c4] = zz;
        }
        return;
    }

    const float* __restrict__ Qb = g_Q + (size_t)z * Sq * Dh;
    const float* __restrict__ Kb = g_K + (size_t)z * Sq * Dh;

    float acc[4][4][4];
    ACC_INIT(acc);
    run_mma<true>(Qb, Dh, i0, Kb, Dh, j0, Dh, acc);

    EPI_PREAMBLE;
    const float rscale = 1.0f / sqrtf((float)Im);
    const int gi0 = i0 + mBase;
    const int gj0 = j0 + nBase;
    #pragma unroll
    for (int mt = 0; mt < 4; mt++)
        #pragma unroll
        for (int nt = 0; nt < 4; nt++) {
            #pragma unroll
            for (int h = 0; h < 2; h++) {
                int gi = gi0 + mt * 16 + h * 8;
                int gj = gj0 + nt * 8;
                float2 o;
                float v0 = 0.0f, v1 = 0.0f;
                if (gj <= gi) {
                    float s = acc[mt][nt][2 * h] * rscale + g_bias[gi - gj];
                    v0 = (s > 0.0f) ? s * s : 0.0f;
                }
                if (gj + 1 <= gi) {
                    float s = acc[mt][nt][2 * h + 1] * rscale + g_bias[gi - gj - 1];
                    v1 = (s > 0.0f) ? s * s : 0.0f;
                }
                o.x = v0; o.y = v1;
                *(float2*)&Ab[(size_t)gi * Sq + gj] = o;
            }
        }
}

// ---------------------------------------------------------------------------
// O[b] = (A[b] @ V[b]) * G[b].   Causal: k-loop limited to rowBlock+128.
// ---------------------------------------------------------------------------
__global__ void __launch_bounds__(NT, 2)
gemm_av_gate_kernel()
{
    const int z = blockIdx.z;
    const float* __restrict__ A = g_A + (size_t)z * Sq * Sq;
    const float* __restrict__ V = g_V + (size_t)z * Sq * Im;

    float acc[4][4][4];
    ACC_INIT(acc);
    const int kEnd = blockIdx.y * BM + BM;
    run_mma<false>(A, Sq, blockIdx.y * BM, V, Im, blockIdx.x * BN, kEnd, acc);

    EPI_PREAMBLE;
    const int row0 = z * Sq + blockIdx.y * BM + mBase;
    const int col0 = blockIdx.x * BN + nBase;
    #pragma unroll
    for (int mt = 0; mt < 4; mt++)
        #pragma unroll
        for (int nt = 0; nt < 4; nt++) {
            int c = col0 + nt * 8;
            #pragma unroll
            for (int h = 0; h < 2; h++) {
                int r = row0 + mt * 16 + h * 8;
                size_t idx = (size_t)r * Im + c;
                float2 g = *(const float2*)&g_G[idx];
                float2 o;
                o.x = acc[mt][nt][2 * h + 0] * g.x;
                o.y = acc[mt][nt][2 * h + 1] * g.y;
                *(float2*)&g_O[idx] = o;
            }
        }
}

// ---------------------------------------------------------------------------
// out = O @ out_W + out_b
// ---------------------------------------------------------------------------
__global__ void __launch_bounds__(NT, 2)
gemm_out_kernel(const float* __restrict__ W, const float* __restrict__ bias,
                float* __restrict__ out)
{
    float acc[4][4][4];
    ACC_INIT(acc);
    run_mma<false>(g_O, Im, blockIdx.y * BM, W, Dm, blockIdx.x * BN, Im, acc);

    EPI_PREAMBLE;
    const int row0 = blockIdx.y * BM + mBase;
    const int col0 = blockIdx.x * BN + nBase;
    #pragma unroll
    for (int mt = 0; mt < 4; mt++)
        #pragma unroll
        for (int nt = 0; nt < 4; nt++) {
            int c = col0 + nt * 8;
            float b0 = bias[c], b1 = bias[c + 1];
            #pragma unroll
            for (int h = 0; h < 2; h++) {
                int r = row0 + mt * 16 + h * 8;
                float2 o;
                o.x = acc[mt][nt][2 * h + 0] + b0;
                o.y = acc[mt][nt][2 * h + 1] + b1;
                *(float2*)&out[(size_t)r * Dm + c] = o;
            }
        }
}

// ---------------------------------------------------------------------------
// Launch (input order auto-detected from in_sizes[0])
// ---------------------------------------------------------------------------
extern "C" void kernel_launch(void* const* d_in, const int* in_sizes, int n_in,
                              void* d_out, int out_size)
{
    const float *x, *vW, *vb, *gW, *gb, *inW, *inb;
    const float *qg, *qb, *kg, *kb, *oW, *ob, *rel;

    if (in_sizes[0] == Bsz * Sq * Dm) {
        x   = (const float*)d_in[0];
        vW  = (const float*)d_in[1];
        vb  = (const float*)d_in[2];
        gW  = (const float*)d_in[3];
        gb  = (const float*)d_in[4];
        inW = (const float*)d_in[5];
        inb = (const float*)d_in[6];
        qg  = (const float*)d_in[7];
        qb  = (const float*)d_in[8];
        kg  = (const float*)d_in[9];
        kb  = (const float*)d_in[10];
        oW  = (const float*)d_in[11];
        ob  = (const float*)d_in[12];
        rel = (const float*)d_in[13];
    } else {
        gW  = (const float*)d_in[0];
        gb  = (const float*)d_in[1];
        inW = (const float*)d_in[2];
        inb = (const float*)d_in[3];
        kb  = (const float*)d_in[4];
        kg  = (const float*)d_in[5];
        oW  = (const float*)d_in[6];
        ob  = (const float*)d_in[7];
        qb  = (const float*)d_in[8];
        qg  = (const float*)d_in[9];
        rel = (const float*)d_in[10];
        vW  = (const float*)d_in[11];
        vb  = (const float*)d_in[12];
        x   = (const float*)d_in[13];
    }

    float* out = (float*)d_out;

    static bool attr_done = false;
    if (!attr_done) {
        cudaFuncSetAttribute(gemm_silu_kernel,
            cudaFuncAttributeMaxDynamicSharedMemorySize, SMEM_BYTES_N);
        cudaFuncSetAttribute(gemm_qk_kernel,
            cudaFuncAttributeMaxDynamicSharedMemorySize, SMEM_BYTES_N);
        cudaFuncSetAttribute(scores_kernel,
            cudaFuncAttributeMaxDynamicSharedMemorySize, SMEM_BYTES_T);
        cudaFuncSetAttribute(gemm_av_gate_kernel,
            cudaFuncAttributeMaxDynamicSharedMemorySize, SMEM_BYTES_N);
        cudaFuncSetAttribute(gemm_out_kernel,
            cudaFuncAttributeMaxDynamicSharedMemorySize, SMEM_BYTES_N);
        attr_done = true;
    }

    bias_init_kernel<<<(Sq + 255) / 256, 256>>>(rel);

    dim3 blk(NT);
    gemm_silu_kernel<<<dim3(Im / BN, Mtot / BM), blk, SMEM_BYTES_N>>>(x, vW, vb, 0);
    gemm_silu_kernel<<<dim3(Im / BN, Mtot / BM), blk, SMEM_BYTES_N>>>(x, gW, gb, 1);
    gemm_qk_kernel  <<<dim3(1,       Mtot / BM), blk, SMEM_BYTES_N>>>(x, inW, inb, qg, qb, kg, kb);
    scores_kernel   <<<dim3(Sq / BN, Sq / BM, Bsz), blk, SMEM_BYTES_T>>>();
    gemm_av_gate_kernel<<<dim3(Im / BN, Sq / BM, Bsz), blk, SMEM_BYTES_N>>>();
    gemm_out_kernel <<<dim3(Dm / BN, Mtot / BM), blk, SMEM_BYTES_N>>>(oW, ob, out);
}